// round 15
// baseline (speedup 1.0000x reference)
#include <cuda_runtime.h>
#include <cuda_fp16.h>
#include <cstdint>

// 3x3 conv (NCHW fp32, pad 1, +bias) via SINGLE-PASS fp16 mma.sync GEMM.
// R15: B operands bypass smem entirely — prep packs weights in exact
// m16n8k16 B-fragment order (g_wfrag[ob][tap][kk][n8][lane] uint2), main
// loop reads them as coalesced LDG.64 (L1/L2-resident). smem holds A only
// (K=128, 9 stages, double-buffered 16KB). CTA 64px x 128oc, 4 warps
// (32x64 tiles), 3 CTAs/SM.

#define ABUF   16384               // 64px x 128ch fp16
#define SMEMSZ 32768               // 2*ABUF
#define NSTR   445440              // 3480*128

__device__ __align__(16) __half g_xh[14254080];   // [n][r60][w58][c128]
__device__ __align__(16) uint2  g_wfrag[73728];   // [ob][tap][kk8][n8_16][lane32]

__device__ __forceinline__ uint32_t s2u(const void* p) {
    uint32_t a;
    asm("{ .reg .u64 t; cvta.to.shared.u64 t, %1; cvt.u32.u64 %0, t; }" : "=r"(a) : "l"(p));
    return a;
}
__device__ __forceinline__ void cpa16(uint32_t d, const void* s) {
    asm volatile("cp.async.cg.shared.global [%0], [%1], 16;" :: "r"(d), "l"(s) : "memory");
}
__device__ __forceinline__ void ldm4(uint32_t* r, uint32_t a) {
    asm volatile("ldmatrix.sync.aligned.m8n8.x4.shared.b16 {%0,%1,%2,%3}, [%4];"
        : "=r"(r[0]), "=r"(r[1]), "=r"(r[2]), "=r"(r[3]) : "r"(a));
}
__device__ __forceinline__ void mmah(float* d, const uint32_t* a, uint32_t b0, uint32_t b1) {
    asm volatile("mma.sync.aligned.m16n8k16.row.col.f32.f16.f16.f32 "
        "{%0,%1,%2,%3}, {%4,%5,%6,%7}, {%8,%9}, {%0,%1,%2,%3};"
        : "+f"(d[0]), "+f"(d[1]), "+f"(d[2]), "+f"(d[3])
        : "r"(a[0]), "r"(a[1]), "r"(a[2]), "r"(a[3]), "r"(b0), "r"(b1));
}
__device__ __forceinline__ uint32_t pkh(__half a, __half b) {
    __half2 t(a, b);
    return *reinterpret_cast<uint32_t*>(&t);
}

// ---- prep: blocks <3480 convert x (NHWC+halo); else pack w fragments ----
__global__ void prep_kernel(const float* __restrict__ x, const float* __restrict__ w) {
    if (blockIdx.x < 3480) {
        int i = blockIdx.x * 256 + threadIdx.x;       // < 890880
        int wq = i % 58;  i /= 58;
        int r  = i % 60;  i /= 60;
        int c16 = i & 7;
        int n   = i >> 3;
        const int row = r - 1, col = wq - 1;
        const bool v = (unsigned)row < 56u && (unsigned)col < 56u;
        const float* src = x + (((size_t)n * 128 + c16 * 16) * 56 + row) * 56 + col;
        __half hb[16];
#pragma unroll
        for (int j = 0; j < 16; ++j)
            hb[j] = __float2half(v ? __ldg(src + (size_t)j * 3136) : 0.0f);
        size_t base = ((size_t)n * 3480 + r * 58 + wq) * 128 + c16 * 16;
        *(uint4*)(g_xh + base)     = *(uint4*)hb;
        *(uint4*)(g_xh + base + 8) = *(uint4*)(hb + 8);
    } else {
        int i = (blockIdx.x - 3480) * 256 + threadIdx.x;
        if (i < 73728) {
            const int l  = i & 31;  int i2 = i >> 5;
            const int n8 = i2 & 15; int i3 = i2 >> 4;
            const int kk = i3 & 7;  int i4 = i3 >> 3;
            const int tap = i4 % 9, ob = i4 / 9;
            const int oc  = ob * 128 + n8 * 8 + (l >> 2);
            const int ch0 = kk * 16 + 2 * (l & 3);
            const float* wp = w + (size_t)oc * 1152 + tap;     // w[oc][ch][tap]
            __half h0 = __float2half(__ldg(wp + (size_t)ch0 * 9));
            __half h1 = __float2half(__ldg(wp + (size_t)(ch0 + 1) * 9));
            __half h2 = __float2half(__ldg(wp + (size_t)(ch0 + 8) * 9));
            __half h3 = __float2half(__ldg(wp + (size_t)(ch0 + 9) * 9));
            uint2 v2;
            v2.x = pkh(h0, h1);      // b0: k = 16kk+2(l&3), +1 at col n8*8+(l>>2)
            v2.y = pkh(h2, h3);      // b1: same k+8
            g_wfrag[i] = v2;
        }
    }
}

__global__ __launch_bounds__(128, 3)
void conv_mma_kernel(const float* __restrict__ bias, float* __restrict__ out) {
    extern __shared__ __align__(16) char smem[];
    const uint32_t SB = s2u(smem);       // A double buffer only

    const int tid = threadIdx.x;
    const int p0  = blockIdx.x * 64;
    const int ob  = blockIdx.y;
    const int n   = blockIdx.z;

    // A staging map: jj = 16B ch-chunk (0..15), tr = row group (0..7)
    const int jj = tid & 15;
    const int tr = tid >> 4;
    int q[8];
#pragma unroll
    for (int i = 0; i < 8; ++i) {
        int p = p0 + tr + 8 * i;
        q[i] = p + 2 * (p / 56);         // offset in 58-wide padded frame
    }

    // mma map: 4 warps = 2(M) x 2(N); warp tile 32x64
    const int wid = tid >> 5, l = tid & 31;
    const int m0 = (wid & 1) * 32;
    const int n0 = (wid >> 1) * 64;
    const int n8base = n0 >> 3;          // 0 or 8
    const int rA0 = m0 + (l & 15);
    const int ahx = rA0 & 7;
    const int ahi = l >> 4;

    float acc[2][8][4];                  // [m-tile][n8-tile][frag]
#pragma unroll
    for (int a = 0; a < 2; ++a)
#pragma unroll
        for (int b = 0; b < 8; ++b)
#pragma unroll
            for (int c = 0; c < 4; ++c) acc[a][b][c] = 0.0f;

    auto stageA = [&](int t) {
        const uint32_t ab = SB + (uint32_t)(t & 1) * ABUF;
        const __half* src = g_xh + (size_t)n * NSTR
                          + (size_t)((t / 3) * 58 + (t % 3)) * 128 + jj * 8;
#pragma unroll
        for (int i = 0; i < 8; ++i) {
            int r = tr + 8 * i;
            cpa16(ab + (uint32_t)r * 256 + (uint32_t)((jj ^ (r & 7)) << 4),
                  src + (size_t)q[i] * 128);
        }
        asm volatile("cp.async.commit_group;" ::: "memory");
    };

    stageA(0);

#pragma unroll 1
    for (int s = 0; s < 9; ++s) {
        asm volatile("cp.async.wait_group 0;" ::: "memory");
        __syncthreads();
        if (s + 1 < 9) stageA(s + 1);

        const uint32_t ab = SB + (uint32_t)(s & 1) * ABUF;
        const uint2* gw = g_wfrag + (size_t)(ob * 9 + s) * 4096 + l;
#pragma unroll
        for (int kk = 0; kk < 8; ++kk) {
            uint32_t af[2][4];
            const uint32_t ac = (uint32_t)(((kk * 2 + ahi) ^ ahx) << 4);
            ldm4(af[0], ab + (uint32_t)rA0 * 256 + ac);
            ldm4(af[1], ab + (uint32_t)rA0 * 256 + 4096 + ac);
            const uint2* gk = gw + (size_t)(kk * 16 + n8base) * 32;
#pragma unroll
            for (int np = 0; np < 4; ++np) {
                const uint2 bA = __ldg(gk + (size_t)(2 * np) * 32);
                const uint2 bB = __ldg(gk + (size_t)(2 * np + 1) * 32);
                mmah(acc[0][2 * np],     af[0], bA.x, bA.y);
                mmah(acc[0][2 * np + 1], af[0], bB.x, bB.y);
                mmah(acc[1][2 * np],     af[1], bA.x, bA.y);
                mmah(acc[1][2 * np + 1], af[1], bB.x, bB.y);
            }
        }
    }

    // ---- epilogue: +bias, stores (exact cover) ----
    const int rbase = p0 + m0 + (l >> 2);
    const int cb = n0 + (l & 3) * 2;
#pragma unroll
    for (int mt = 0; mt < 2; ++mt)
#pragma unroll
        for (int h2 = 0; h2 < 2; ++h2) {
            const int p = rbase + mt * 16 + h2 * 8;
#pragma unroll
            for (int nt = 0; nt < 8; ++nt) {
                const int oc = ob * 128 + cb + nt * 8;
                float* op = out + ((size_t)n * 256 + oc) * 3136 + p;
                op[0]    = acc[mt][nt][h2 * 2]     + __ldg(&bias[oc]);
                op[3136] = acc[mt][nt][h2 * 2 + 1] + __ldg(&bias[oc + 1]);
            }
        }
}

extern "C" void kernel_launch(void* const* d_in, const int* in_sizes, int n_in,
                              void* d_out, int out_size)
{
    const float* x    = (const float*)d_in[0];
    const float* w    = (const float*)d_in[1];
    const float* bias = (const float*)d_in[2];
    float* out        = (float*)d_out;

    cudaFuncSetAttribute(conv_mma_kernel,
                         cudaFuncAttributeMaxDynamicSharedMemorySize, SMEMSZ);

    prep_kernel<<<3768, 256>>>(x, w);   // 3480 x-blocks + 288 wfrag-blocks
    dim3 grid(49, 2, 32);
    conv_mma_kernel<<<grid, 128, SMEMSZ>>>(bias, out);
}